// round 2
// baseline (speedup 1.0000x reference)
#include <cuda_runtime.h>

#define B 64
#define N 16384
#define M 64

// scratch (device globals — no allocation allowed)
__device__ float g_s[B * N];    // exp(beta*cos) from k1
__device__ float g_wg[B * N];   // ws^sharpen from k2b
__device__ float g_sum[B];      // softmax denominator (atomic)
__device__ float g_psum[B];     // renorm denominator (atomic)

// ---------------------------------------------------------------------------
// k0: zero the atomic accumulators
// ---------------------------------------------------------------------------
__global__ void k0_zero() {
    const int t = threadIdx.x;
    if (t < B) { g_sum[t] = 0.0f; g_psum[t] = 0.0f; }
}

// ---------------------------------------------------------------------------
// k1: exp(beta*cos(key, mem_row)) per row + per-batch sum (atomic per block).
// 4 lanes per row, each lane loads 4x float4 (64B), 2 rows per thread.
// Block = 256 threads -> 128 rows. Grid = (N/128, B).
// ---------------------------------------------------------------------------
__global__ __launch_bounds__(256) void k1_logits(
    const float* __restrict__ key,    // [B, M]
    const float* __restrict__ beta,   // [B, 1]
    const float* __restrict__ mem)    // [B, N, M]
{
    const int b    = blockIdx.y;
    const int tid  = threadIdx.x;
    const int l    = tid & 3;    // lane within 4-lane row group
    const int rsub = tid >> 2;   // 0..63
    const int row0 = blockIdx.x * 128;

    // key chunks for this lane (float4 indices l, l+4, l+8, l+12)
    const float4* kp = reinterpret_cast<const float4*>(key + b * M);
    float4 k4[4];
#pragma unroll
    for (int j = 0; j < 4; ++j) k4[j] = kp[l + 4 * j];

    float ks = 0.0f;
#pragma unroll
    for (int j = 0; j < 4; ++j)
        ks += k4[j].x * k4[j].x + k4[j].y * k4[j].y
            + k4[j].z * k4[j].z + k4[j].w * k4[j].w;

    // front-batched loads: 8 LDG.128 in flight
    float4 m4[2][4];
#pragma unroll
    for (int u = 0; u < 2; ++u) {
        const int row = row0 + u * 64 + rsub;
        const float4* mp = reinterpret_cast<const float4*>(
            mem + ((size_t)b * N + row) * M);
#pragma unroll
        for (int j = 0; j < 4; ++j) m4[u][j] = mp[l + 4 * j];
    }

    float dot[2] = {0.0f, 0.0f}, ms[2] = {0.0f, 0.0f};
#pragma unroll
    for (int u = 0; u < 2; ++u)
#pragma unroll
        for (int j = 0; j < 4; ++j) {
            dot[u] += k4[j].x * m4[u][j].x + k4[j].y * m4[u][j].y
                    + k4[j].z * m4[u][j].z + k4[j].w * m4[u][j].w;
            ms[u]  += m4[u][j].x * m4[u][j].x + m4[u][j].y * m4[u][j].y
                    + m4[u][j].z * m4[u][j].z + m4[u][j].w * m4[u][j].w;
        }

    // width-4 xor reductions (lane bits 0..1 stay in the 4-group)
#pragma unroll
    for (int off = 1; off <= 2; off <<= 1) {
        ks     += __shfl_xor_sync(0xFFFFFFFFu, ks,     off);
        dot[0] += __shfl_xor_sync(0xFFFFFFFFu, dot[0], off);
        dot[1] += __shfl_xor_sync(0xFFFFFFFFu, dot[1], off);
        ms[0]  += __shfl_xor_sync(0xFFFFFFFFu, ms[0],  off);
        ms[1]  += __shfl_xor_sync(0xFFFFFFFFu, ms[1],  off);
    }

    float esum = 0.0f;
    if (l == 0) {
        const float kn = sqrtf(ks);
        const float be = __ldg(beta + b);
#pragma unroll
        for (int u = 0; u < 2; ++u) {
            const int row = row0 + u * 64 + rsub;
            const float denom = fmaxf(kn * sqrtf(ms[u]), 1e-8f);
            const float e = __expf(be * (dot[u] / denom));
            g_s[b * N + row] = e;
            esum += e;
        }
    }

    // block reduction of exp partials -> one atomicAdd per block
    __shared__ float sred[8];
#pragma unroll
    for (int o = 16; o > 0; o >>= 1)
        esum += __shfl_xor_sync(0xFFFFFFFFu, esum, o);
    if ((tid & 31) == 0) sred[tid >> 5] = esum;
    __syncthreads();
    if (tid == 0) {
        float s = 0.0f;
#pragma unroll
        for (int w = 0; w < 8; ++w) s += sred[w];
        atomicAdd(&g_sum[b], s);
    }
}

// ---------------------------------------------------------------------------
// k2b: full-chip elementwise: gate + circular 3-tap shift (wg recomputed at
// the 3 taps — pure elementwise fn of g_s/last) + pow; partial renorm sums.
// Grid = (N/2048, B) = 512 blocks.
// ---------------------------------------------------------------------------
#define K2K 8
__global__ __launch_bounds__(256) void k2b_shiftpow(
    const float* __restrict__ gate,     // [B,1]
    const float* __restrict__ shift,    // [B,3]
    const float* __restrict__ sharpen,  // [B,1]
    const float* __restrict__ last)     // [B,N]
{
    const int b    = blockIdx.y;
    const int base = blockIdx.x * (256 * K2K);
    const int tid  = threadIdx.x;

    const float g    = __ldg(gate + b);
    const float og   = 1.0f - g;
    const float invS = 1.0f / g_sum[b];
    const float gS   = g * invS;
    const float s0   = __ldg(shift + b * 3 + 0);
    const float s1   = __ldg(shift + b * 3 + 1);
    const float s2   = __ldg(shift + b * 3 + 2);
    const float sh   = __ldg(sharpen + b);

    const float* __restrict__ sp = g_s  + b * N;
    const float* __restrict__ lp = last + (size_t)b * N;
    float* __restrict__ wp = g_wg + b * N;

    float psum = 0.0f;
#pragma unroll
    for (int k = 0; k < K2K; ++k) {
        const int i   = base + tid + k * 256;
        const int im1 = (i + N - 1) & (N - 1);
        const int ip1 = (i + 1) & (N - 1);
        const float wm = fmaf(gS, sp[im1], og * lp[im1]);
        const float wc = fmaf(gS, sp[i],   og * lp[i]);
        const float wx = fmaf(gS, sp[ip1], og * lp[ip1]);
        const float ws = s0 * wm + s1 * wc + s2 * wx;
        const float p  = __powf(ws, sh);
        wp[i] = p;
        psum += p;
    }

    __shared__ float sred[8];
#pragma unroll
    for (int o = 16; o > 0; o >>= 1)
        psum += __shfl_xor_sync(0xFFFFFFFFu, psum, o);
    if ((tid & 31) == 0) sred[tid >> 5] = psum;
    __syncthreads();
    if (tid == 0) {
        float s = 0.0f;
#pragma unroll
        for (int w = 0; w < 8; ++w) s += sred[w];
        atomicAdd(&g_psum[b], s);
    }
}

// ---------------------------------------------------------------------------
// k2c: normalize. Grid = (N/2048, B).
// ---------------------------------------------------------------------------
__global__ __launch_bounds__(256) void k2c_norm(float* __restrict__ out) {
    const int b    = blockIdx.y;
    const int base = blockIdx.x * (256 * K2K);
    const float invP = 1.0f / (g_psum[b] + 1e-16f);
    const float* __restrict__ wp = g_wg + b * N;
    float* __restrict__ op = out + (size_t)b * N;
#pragma unroll
    for (int k = 0; k < K2K; ++k) {
        const int i = base + threadIdx.x + k * 256;
        op[i] = wp[i] * invP;
    }
}

extern "C" void kernel_launch(void* const* d_in, const int* in_sizes, int n_in,
                              void* d_out, int out_size) {
    const float* key     = (const float*)d_in[0];  // [B,M]
    const float* beta    = (const float*)d_in[1];  // [B,1]
    const float* gate    = (const float*)d_in[2];  // [B,1]
    const float* shift   = (const float*)d_in[3];  // [B,3]
    const float* sharpen = (const float*)d_in[4];  // [B,1]
    const float* last    = (const float*)d_in[5];  // [B,N]
    const float* mem     = (const float*)d_in[6];  // [B,N,M]
    float* out = (float*)d_out;

    k0_zero<<<1, 64>>>();
    dim3 g1(N / 128, B);
    k1_logits<<<g1, 256>>>(key, beta, mem);
    dim3 g2(N / (256 * K2K), B);
    k2b_shiftpow<<<g2, 256>>>(gate, shift, sharpen, last);
    k2c_norm<<<g2, 256>>>(out);
}

// round 3
// speedup vs baseline: 1.0646x; 1.0646x over previous
#include <cuda_runtime.h>

#define B 64
#define N 16384
#define M 64

// scratch (device global — no allocation allowed)
__device__ float g_s[B * N];    // exp(beta*cos) from k1

// ---------------------------------------------------------------------------
// k1: exp(beta*cos(key, mem_row)) per row. 4 lanes per row, each lane loads
// 4x float4 (64B of the 256B row); 4 rows per thread -> 16 LDG.128 in flight.
// Block = 256 threads -> 256 rows. Grid = (N/256, B).
// No max-subtraction needed: |beta*cos| < 5 so exp is well-conditioned, and
// softmax is shift-invariant.
// ---------------------------------------------------------------------------
__global__ __launch_bounds__(256) void k1_logits(
    const float* __restrict__ key,    // [B, M]
    const float* __restrict__ beta,   // [B, 1]
    const float* __restrict__ mem)    // [B, N, M]
{
    const int b    = blockIdx.y;
    const int tid  = threadIdx.x;
    const int l    = tid & 3;    // lane within 4-lane row group
    const int grp  = tid >> 2;   // 0..63
    const int row0 = blockIdx.x * 256;

    // key chunks for this lane (float4 indices l, l+4, l+8, l+12)
    const float4* kp = reinterpret_cast<const float4*>(key + b * M);
    float4 k4[4];
#pragma unroll
    for (int j = 0; j < 4; ++j) k4[j] = kp[l + 4 * j];

    float ks = 0.0f;
#pragma unroll
    for (int j = 0; j < 4; ++j)
        ks += k4[j].x * k4[j].x + k4[j].y * k4[j].y
            + k4[j].z * k4[j].z + k4[j].w * k4[j].w;

    // front-batched loads: 16 LDG.128 in flight
    float4 m4[4][4];
#pragma unroll
    for (int u = 0; u < 4; ++u) {
        const int row = row0 + u * 64 + grp;
        const float4* mp = reinterpret_cast<const float4*>(
            mem + ((size_t)b * N + row) * M);
#pragma unroll
        for (int j = 0; j < 4; ++j) m4[u][j] = mp[l + 4 * j];
    }

    float dot[4] = {0.f, 0.f, 0.f, 0.f}, ms[4] = {0.f, 0.f, 0.f, 0.f};
#pragma unroll
    for (int u = 0; u < 4; ++u)
#pragma unroll
        for (int j = 0; j < 4; ++j) {
            dot[u] += k4[j].x * m4[u][j].x + k4[j].y * m4[u][j].y
                    + k4[j].z * m4[u][j].z + k4[j].w * m4[u][j].w;
            ms[u]  += m4[u][j].x * m4[u][j].x + m4[u][j].y * m4[u][j].y
                    + m4[u][j].z * m4[u][j].z + m4[u][j].w * m4[u][j].w;
        }

    // width-4 xor reductions (lane bits 0..1 stay in the 4-group)
#pragma unroll
    for (int off = 1; off <= 2; off <<= 1) {
        ks += __shfl_xor_sync(0xFFFFFFFFu, ks, off);
#pragma unroll
        for (int u = 0; u < 4; ++u) {
            dot[u] += __shfl_xor_sync(0xFFFFFFFFu, dot[u], off);
            ms[u]  += __shfl_xor_sync(0xFFFFFFFFu, ms[u],  off);
        }
    }

    if (l == 0) {
        const float kn = sqrtf(ks);
        const float be = __ldg(beta + b);
#pragma unroll
        for (int u = 0; u < 4; ++u) {
            const int row = row0 + u * 64 + grp;
            const float denom = fmaxf(kn * sqrtf(ms[u]), 1e-8f);
            g_s[b * N + row] = __expf(be * (dot[u] / denom));
        }
    }
}

// ---------------------------------------------------------------------------
// k2: per-batch: sum(exp) -> gate -> circular 3-tap shift (via 64KB smem
// staging) -> sharpen -> renorm -> out. One block per batch, 1024 threads,
// float4 everywhere, wg kept in registers (smem serves only the +-1 halo).
// ---------------------------------------------------------------------------
extern __shared__ float smw[];  // N floats = 64 KB

__global__ __launch_bounds__(1024) void k2_address(
    const float* __restrict__ gate,     // [B,1]
    const float* __restrict__ shift,    // [B,3]
    const float* __restrict__ sharpen,  // [B,1]
    const float* __restrict__ last,     // [B,N]
    float* __restrict__ out)            // [B,N]
{
    const int b   = blockIdx.x;
    const int tid = threadIdx.x;

    __shared__ float red[32];
    __shared__ float bc[2];

    const int warp = tid >> 5;
    const int lane = tid & 31;

    const float4* sp4 = reinterpret_cast<const float4*>(g_s  + b * N);
    const float4* lp4 = reinterpret_cast<const float4*>(last + (size_t)b * N);

    // ---- front-batched loads: exp values + last_address ----
    float4 v4[4], l4[4];
#pragma unroll
    for (int k = 0; k < 4; ++k) {
        v4[k] = sp4[tid + k * 1024];
        l4[k] = lp4[tid + k * 1024];
    }

    // ---- softmax denominator ----
    float s = 0.f;
#pragma unroll
    for (int k = 0; k < 4; ++k)
        s += v4[k].x + v4[k].y + v4[k].z + v4[k].w;
#pragma unroll
    for (int o = 16; o > 0; o >>= 1)
        s += __shfl_xor_sync(0xFFFFFFFFu, s, o);
    if (lane == 0) red[warp] = s;
    __syncthreads();
    if (tid < 32) {
        float x = red[tid];
#pragma unroll
        for (int o = 16; o > 0; o >>= 1)
            x += __shfl_xor_sync(0xFFFFFFFFu, x, o);
        if (tid == 0) bc[0] = x;
    }
    __syncthreads();

    const float g  = __ldg(gate + b);
    const float gS = g / bc[0];
    const float og = 1.0f - g;

    // ---- gate interpolation: wg in registers, staged to smem for halo ----
    float4* sm4 = reinterpret_cast<float4*>(smw);
#pragma unroll
    for (int k = 0; k < 4; ++k) {
        v4[k].x = fmaf(gS, v4[k].x, og * l4[k].x);
        v4[k].y = fmaf(gS, v4[k].y, og * l4[k].y);
        v4[k].z = fmaf(gS, v4[k].z, og * l4[k].z);
        v4[k].w = fmaf(gS, v4[k].w, og * l4[k].w);
        sm4[tid + k * 1024] = v4[k];
    }
    __syncthreads();

    // ---- circular 3-tap shift + sharpening ----
    const float s0 = __ldg(shift + b * 3 + 0);
    const float s1 = __ldg(shift + b * 3 + 1);
    const float s2 = __ldg(shift + b * 3 + 2);
    const float sh = __ldg(sharpen + b);

    float psum = 0.f;
#pragma unroll
    for (int k = 0; k < 4; ++k) {
        const int i4   = tid + k * 1024;
        const int base = 4 * i4;
        const float wl = smw[(base - 1) & (N - 1)];  // left halo
        const float wr = smw[(base + 4) & (N - 1)];  // right halo
        const float4 w = v4[k];
        float4 p;
        p.x = __powf(s0 * wl  + s1 * w.x + s2 * w.y, sh);
        p.y = __powf(s0 * w.x + s1 * w.y + s2 * w.z, sh);
        p.z = __powf(s0 * w.y + s1 * w.z + s2 * w.w, sh);
        p.w = __powf(s0 * w.z + s1 * w.w + s2 * wr,  sh);
        v4[k] = p;
        psum += p.x + p.y + p.z + p.w;
    }

#pragma unroll
    for (int o = 16; o > 0; o >>= 1)
        psum += __shfl_xor_sync(0xFFFFFFFFu, psum, o);
    if (lane == 0) red[warp] = psum;
    __syncthreads();
    if (tid < 32) {
        float x = red[tid];
#pragma unroll
        for (int o = 16; o > 0; o >>= 1)
            x += __shfl_xor_sync(0xFFFFFFFFu, x, o);
        if (tid == 0) bc[1] = x;
    }
    __syncthreads();
    const float invP = 1.0f / (bc[1] + 1e-16f);

    float4* op4 = reinterpret_cast<float4*>(out + (size_t)b * N);
#pragma unroll
    for (int k = 0; k < 4; ++k) {
        float4 p = v4[k];
        p.x *= invP; p.y *= invP; p.z *= invP; p.w *= invP;
        op4[tid + k * 1024] = p;
    }
}

extern "C" void kernel_launch(void* const* d_in, const int* in_sizes, int n_in,
                              void* d_out, int out_size) {
    const float* key     = (const float*)d_in[0];  // [B,M]
    const float* beta    = (const float*)d_in[1];  // [B,1]
    const float* gate    = (const float*)d_in[2];  // [B,1]
    const float* shift   = (const float*)d_in[3];  // [B,3]
    const float* sharpen = (const float*)d_in[4];  // [B,1]
    const float* last    = (const float*)d_in[5];  // [B,N]
    const float* mem     = (const float*)d_in[6];  // [B,N,M]
    float* out = (float*)d_out;

    static bool smem_set = false;
    if (!smem_set) {
        cudaFuncSetAttribute(k2_address,
                             cudaFuncAttributeMaxDynamicSharedMemorySize,
                             N * sizeof(float));
        smem_set = true;
    }

    dim3 g1(N / 256, B);
    k1_logits<<<g1, 256>>>(key, beta, mem);
    k2_address<<<B, 1024, N * sizeof(float)>>>(gate, shift, sharpen, last, out);
}

// round 4
// speedup vs baseline: 1.1191x; 1.0512x over previous
#include <cuda_runtime.h>

#define B 64
#define N 16384
#define M 64
#define FULLM 0xFFFFFFFFu

// scratch (device globals — no allocation allowed)
__device__ float g_s[B * N];       // exp(beta*cos) from k1
__device__ float g_part[B * 64];   // per-block partial sums of exp (k1 grid.x = 64)

// ---------------------------------------------------------------------------
// k1: exp(beta*cos(key, mem_row)) per row + deterministic per-block partial
// sum. 4 lanes per row, each lane loads 4x float4 (64B of the 256B row);
// 4 rows per thread -> 16 LDG.128 in flight, streaming (.cs).
// Block = 256 threads -> 256 rows. Grid = (N/256, B) = (64, B).
// ---------------------------------------------------------------------------
__global__ __launch_bounds__(256) void k1_logits(
    const float* __restrict__ key,    // [B, M]
    const float* __restrict__ beta,   // [B, 1]
    const float* __restrict__ mem)    // [B, N, M]
{
    const int b    = blockIdx.y;
    const int tid  = threadIdx.x;
    const int l    = tid & 3;    // lane within 4-lane row group
    const int grp  = tid >> 2;   // 0..63
    const int row0 = blockIdx.x * 256;

    const float4* kp = reinterpret_cast<const float4*>(key + b * M);
    float4 k4[4];
#pragma unroll
    for (int j = 0; j < 4; ++j) k4[j] = kp[l + 4 * j];

    float ks = 0.0f;
#pragma unroll
    for (int j = 0; j < 4; ++j)
        ks += k4[j].x * k4[j].x + k4[j].y * k4[j].y
            + k4[j].z * k4[j].z + k4[j].w * k4[j].w;

    // front-batched streaming loads: 16 LDG.128.CS in flight
    float4 m4[4][4];
#pragma unroll
    for (int u = 0; u < 4; ++u) {
        const int row = row0 + u * 64 + grp;
        const float4* mp = reinterpret_cast<const float4*>(
            mem + ((size_t)b * N + row) * M);
#pragma unroll
        for (int j = 0; j < 4; ++j) m4[u][j] = __ldcs(mp + l + 4 * j);
    }

    float dot[4] = {0.f, 0.f, 0.f, 0.f}, ms[4] = {0.f, 0.f, 0.f, 0.f};
#pragma unroll
    for (int u = 0; u < 4; ++u)
#pragma unroll
        for (int j = 0; j < 4; ++j) {
            dot[u] += k4[j].x * m4[u][j].x + k4[j].y * m4[u][j].y
                    + k4[j].z * m4[u][j].z + k4[j].w * m4[u][j].w;
            ms[u]  += m4[u][j].x * m4[u][j].x + m4[u][j].y * m4[u][j].y
                    + m4[u][j].z * m4[u][j].z + m4[u][j].w * m4[u][j].w;
        }

#pragma unroll
    for (int off = 1; off <= 2; off <<= 1) {
        ks += __shfl_xor_sync(FULLM, ks, off);
#pragma unroll
        for (int u = 0; u < 4; ++u) {
            dot[u] += __shfl_xor_sync(FULLM, dot[u], off);
            ms[u]  += __shfl_xor_sync(FULLM, ms[u],  off);
        }
    }

    float esum = 0.0f;
    if (l == 0) {
        const float kn = sqrtf(ks);
        const float be = __ldg(beta + b);
#pragma unroll
        for (int u = 0; u < 4; ++u) {
            const int row = row0 + u * 64 + grp;
            const float denom = fmaxf(kn * sqrtf(ms[u]), 1e-8f);
            const float e = __expf(be * (dot[u] / denom));
            g_s[b * N + row] = e;
            esum += e;
        }
    }

    // deterministic per-block partial sum
    __shared__ float sred[8];
#pragma unroll
    for (int o = 16; o > 0; o >>= 1)
        esum += __shfl_xor_sync(FULLM, esum, o);
    if ((tid & 31) == 0) sred[tid >> 5] = esum;
    __syncthreads();
    if (tid == 0) {
        float s = 0.0f;
#pragma unroll
        for (int w = 0; w < 8; ++w) s += sred[w];
        g_part[b * 64 + blockIdx.x] = s;
    }
}

// ---------------------------------------------------------------------------
// k2: per-batch softmax-normalize + gate + circular 3-tap shift + sharpen +
// renorm. One block (1024 thr) per batch. Warp-contiguous layout: warp w owns
// float4s [w*128, (w+1)*128); lane l holds float4 k*32+l for k=0..3 ->
// perfectly coalesced loads; 3-tap halo via register shuffles, warp edges via
// 64-float smem. Softmax denom comes precomputed from k1 partials.
// ---------------------------------------------------------------------------
__global__ __launch_bounds__(1024) void k2_address(
    const float* __restrict__ gate,     // [B,1]
    const float* __restrict__ shift,    // [B,3]
    const float* __restrict__ sharpen,  // [B,1]
    const float* __restrict__ last,     // [B,N]
    float* __restrict__ out)            // [B,N]
{
    const int b    = blockIdx.x;
    const int tid  = threadIdx.x;
    const int warp = tid >> 5;
    const int lane = tid & 31;

    __shared__ float red[32];
    __shared__ float bc[2];
    __shared__ float edgeL[32];  // first element of each warp's span (gated)
    __shared__ float edgeR[32];  // last  element of each warp's span (gated)

    const float4* sp4 = reinterpret_cast<const float4*>(g_s  + b * N);
    const float4* lp4 = reinterpret_cast<const float4*>(last + (size_t)b * N);

    // ---- front-batched coalesced loads ----
    float4 v4[4], l4[4];
#pragma unroll
    for (int k = 0; k < 4; ++k) {
        const int idx = warp * 128 + k * 32 + lane;
        v4[k] = sp4[idx];
        l4[k] = lp4[idx];
    }

    // ---- softmax denominator from k1 partials (warp 0, overlapped) ----
    if (warp == 0) {
        float s = g_part[b * 64 + lane] + g_part[b * 64 + 32 + lane];
#pragma unroll
        for (int o = 16; o > 0; o >>= 1)
            s += __shfl_xor_sync(FULLM, s, o);
        if (lane == 0) bc[0] = s;
    }
    __syncthreads();

    const float g  = __ldg(gate + b);
    const float gS = g / bc[0];
    const float og = 1.0f - g;

    // ---- gate interpolation in registers ----
    float4 w4[4];
#pragma unroll
    for (int k = 0; k < 4; ++k) {
        w4[k].x = fmaf(gS, v4[k].x, og * l4[k].x);
        w4[k].y = fmaf(gS, v4[k].y, og * l4[k].y);
        w4[k].z = fmaf(gS, v4[k].z, og * l4[k].z);
        w4[k].w = fmaf(gS, v4[k].w, og * l4[k].w);
    }

    // warp-edge elements (for cross-warp halo, incl. circular batch wrap)
    if (lane == 0)  edgeL[warp] = w4[0].x;
    if (lane == 31) edgeR[warp] = w4[3].w;
    __syncthreads();

    const float s0 = __ldg(shift + b * 3 + 0);
    const float s1 = __ldg(shift + b * 3 + 1);
    const float s2 = __ldg(shift + b * 3 + 2);
    const float sh = __ldg(sharpen + b);

    const float wrapL = edgeR[(warp + 31) & 31];  // element before this warp's span
    const float wrapR = edgeL[(warp + 1) & 31];   // element after  this warp's span

    // ---- circular 3-tap conv + sharpen, halos via shuffles ----
    float psum = 0.0f;
    float4 p4[4];
#pragma unroll
    for (int k = 0; k < 4; ++k) {
        // left neighbor of w4[k].x : lane-1's w4[k].w ; lane0: prev k's lane31 .w ; k0: warp edge
        const float prevw = __shfl_sync(FULLM, w4[(k + 3) & 3].w, 31);
        float left = __shfl_up_sync(FULLM, w4[k].w, 1);
        if (lane == 0) left = (k == 0) ? wrapL : prevw;
        // right neighbor of w4[k].w : lane+1's w4[k].x ; lane31: next k's lane0 .x ; k3: warp edge
        const float nextx = __shfl_sync(FULLM, w4[(k + 1) & 3].x, 0);
        float right = __shfl_down_sync(FULLM, w4[k].x, 1);
        if (lane == 31) right = (k == 3) ? wrapR : nextx;

        p4[k].x = __powf(s0 * left    + s1 * w4[k].x + s2 * w4[k].y, sh);
        p4[k].y = __powf(s0 * w4[k].x + s1 * w4[k].y + s2 * w4[k].z, sh);
        p4[k].z = __powf(s0 * w4[k].y + s1 * w4[k].z + s2 * w4[k].w, sh);
        p4[k].w = __powf(s0 * w4[k].z + s1 * w4[k].w + s2 * right,  sh);
        psum += p4[k].x + p4[k].y + p4[k].z + p4[k].w;
    }

    // ---- renorm sum ----
#pragma unroll
    for (int o = 16; o > 0; o >>= 1)
        psum += __shfl_xor_sync(FULLM, psum, o);
    if (lane == 0) red[warp] = psum;
    __syncthreads();
    if (tid < 32) {
        float x = red[tid];
#pragma unroll
        for (int o = 16; o > 0; o >>= 1)
            x += __shfl_xor_sync(FULLM, x, o);
        if (tid == 0) bc[1] = x;
    }
    __syncthreads();
    const float invP = 1.0f / (bc[1] + 1e-16f);

    float4* op4 = reinterpret_cast<float4*>(out + (size_t)b * N);
#pragma unroll
    for (int k = 0; k < 4; ++k) {
        float4 p = p4[k];
        p.x *= invP; p.y *= invP; p.z *= invP; p.w *= invP;
        op4[warp * 128 + k * 32 + lane] = p;
    }
}

extern "C" void kernel_launch(void* const* d_in, const int* in_sizes, int n_in,
                              void* d_out, int out_size) {
    const float* key     = (const float*)d_in[0];  // [B,M]
    const float* beta    = (const float*)d_in[1];  // [B,1]
    const float* gate    = (const float*)d_in[2];  // [B,1]
    const float* shift   = (const float*)d_in[3];  // [B,3]
    const float* sharpen = (const float*)d_in[4];  // [B,1]
    const float* last    = (const float*)d_in[5];  // [B,N]
    const float* mem     = (const float*)d_in[6];  // [B,N,M]
    float* out = (float*)d_out;

    dim3 g1(N / 256, B);
    k1_logits<<<g1, 256>>>(key, beta, mem);
    k2_address<<<B, 1024>>>(gate, shift, sharpen, last, out);
}